// round 1
// baseline (speedup 1.0000x reference)
#include <cuda_runtime.h>
#include <cstdio>

// Problem constants
#define NN   50000
#define EE   400000
#define INC  64
#define HIDC 64
#define NH   4
#define LATC 32
#define HC1  256   // H*HID for conv1/conv2 outputs
#define HCM  64    // combined mu|lv width (2 heads x 32)

// ---------------- scratch (static device globals; no allocation) ------------
__device__ float g_hA[(size_t)NN * HC1];   // GEMM output (pre-attention h)
__device__ float g_hB[(size_t)NN * HC1];   // aggregated layer output
__device__ float g_hC[(size_t)NN * HCM];   // mu|lv GEMM output
__device__ float g_aggm[(size_t)NN * HCM]; // mu|lv aggregated (+bias)
__device__ float g_zd[(size_t)NN * HIDC];  // decoder hidden
__device__ float g_ss[NN * NH];            // s_src
__device__ float g_sd[NN * NH];            // s_dst
__device__ int   g_cnt[NN];
__device__ int   g_off[NN + 1];
__device__ int   g_cur[NN];
__device__ int   g_csr[EE];
__device__ float g_Wml[HC1 * HCM];         // [Wmu | Wlv] packed [256,64]
__device__ float g_ams[HCM];               // a_src_mu | a_src_lv
__device__ float g_amd[HCM];               // a_dst_mu | a_dst_lv
__device__ float g_bml[HCM];               // b_mu | b_lv

// ---------------- small utility kernels -------------------------------------
__global__ void k_zero(int* c, int n) {
    int i = blockIdx.x * blockDim.x + threadIdx.x;
    if (i < n) c[i] = 0;
}

__global__ void k_deg(const int* __restrict__ dst, int* __restrict__ cnt, int e) {
    int i = blockIdx.x * blockDim.x + threadIdx.x;
    if (i < e) atomicAdd(&cnt[dst[i]], 1);
}

// single-block exclusive scan (warp-shuffle based), also writes cur = off
__global__ void k_scan(const int* __restrict__ cnt, int* __restrict__ off,
                       int* __restrict__ cur, int n) {
    __shared__ int warpsums[32];
    __shared__ int s_carry;
    const int tid = threadIdx.x, lane = tid & 31, wid = tid >> 5;
    if (tid == 0) s_carry = 0;
    __syncthreads();
    for (int base = 0; base < n; base += blockDim.x) {
        int i = base + tid;
        int v = (i < n) ? cnt[i] : 0;
        int x = v;
        #pragma unroll
        for (int o = 1; o < 32; o <<= 1) {
            int t = __shfl_up_sync(~0u, x, o);
            if (lane >= o) x += t;
        }
        if (lane == 31) warpsums[wid] = x;
        __syncthreads();
        if (wid == 0) {
            int w = warpsums[lane];
            #pragma unroll
            for (int o = 1; o < 32; o <<= 1) {
                int t = __shfl_up_sync(~0u, w, o);
                if (lane >= o) w += t;
            }
            warpsums[lane] = w;
        }
        __syncthreads();
        int warpoff = (wid == 0) ? 0 : warpsums[wid - 1];
        int carry = s_carry;
        int excl = carry + warpoff + x - v;
        if (i < n) { off[i] = excl; cur[i] = excl; }
        __syncthreads();
        if (tid == blockDim.x - 1) s_carry = carry + warpsums[31];
        __syncthreads();
    }
    if (tid == 0) off[n] = s_carry;
}

__global__ void k_scatter(const int* __restrict__ src, const int* __restrict__ dst,
                          int* __restrict__ cur, int* __restrict__ csr, int e) {
    int i = blockIdx.x * blockDim.x + threadIdx.x;
    if (i < e) {
        int d = dst[i];
        int p = atomicAdd(&cur[d], 1);
        csr[p] = src[i];
    }
}

// pack [Wmu|Wlv] and concat a / bias vectors for the fused mu|lv layer
__global__ void k_pack(const float* __restrict__ Wmu, const float* __restrict__ Wlv,
                       const float* __restrict__ asmu, const float* __restrict__ aslv,
                       const float* __restrict__ admu, const float* __restrict__ adlv,
                       const float* __restrict__ bmu, const float* __restrict__ blv) {
    int i = blockIdx.x * blockDim.x + threadIdx.x;
    if (i < HC1 * HCM) {
        int k = i >> 6, c = i & 63;
        g_Wml[i] = (c < 32) ? Wmu[k * 32 + c] : Wlv[k * 32 + (c - 32)];
    }
    if (i < HCM) {
        g_ams[i] = (i < 32) ? asmu[i] : aslv[i - 32];
        g_amd[i] = (i < 32) ? admu[i] : adlv[i - 32];
        g_bml[i] = (i < 32) ? bmu[i]  : blv[i - 32];
    }
}

// ---------------- SGEMM (fp32, tiled, register-blocked) ----------------------
template <int BM, int BN, int BK, int TM, int TN, bool BIAS, bool RELU>
__global__ void k_gemm(const float* __restrict__ A, const float* __restrict__ B,
                       const float* __restrict__ bias, float* __restrict__ C,
                       int M, int Ncols, int K) {
    constexpr int THREADS = (BM / TM) * (BN / TN);
    __shared__ float As[BK][BM + 4];
    __shared__ float Bs[BK][BN];
    const int tid  = threadIdx.x;
    const int brow = blockIdx.x * BM;
    const int bcol = blockIdx.y * BN;
    const int tcol = tid % (BN / TN);
    const int trow = tid / (BN / TN);

    float acc[TM][TN];
    #pragma unroll
    for (int i = 0; i < TM; i++)
        #pragma unroll
        for (int j = 0; j < TN; j++) acc[i][j] = 0.f;

    for (int kt = 0; kt < K; kt += BK) {
        constexpr int AV = BM * BK / 4;
        #pragma unroll
        for (int l = 0; l < AV / THREADS; l++) {
            int v = tid + l * THREADS;
            int r = v / (BK / 4);
            int kk = (v % (BK / 4)) * 4;
            float4 av = make_float4(0.f, 0.f, 0.f, 0.f);
            int gr = brow + r;
            if (gr < M) av = *(const float4*)(A + (size_t)gr * K + kt + kk);
            As[kk + 0][r] = av.x; As[kk + 1][r] = av.y;
            As[kk + 2][r] = av.z; As[kk + 3][r] = av.w;
        }
        constexpr int BV = BK * BN / 4;
        #pragma unroll
        for (int l = 0; l < BV / THREADS; l++) {
            int v = tid + l * THREADS;
            int r = v / (BN / 4);
            int cc = (v % (BN / 4)) * 4;
            *(float4*)&Bs[r][cc] = *(const float4*)(B + (size_t)(kt + r) * Ncols + bcol + cc);
        }
        __syncthreads();
        #pragma unroll
        for (int k = 0; k < BK; k++) {
            float ra[TM], rb[TN];
            #pragma unroll
            for (int i = 0; i < TM; i += 4) {
                float4 t = *(const float4*)&As[k][trow * TM + i];
                ra[i] = t.x; ra[i + 1] = t.y; ra[i + 2] = t.z; ra[i + 3] = t.w;
            }
            #pragma unroll
            for (int j = 0; j < TN; j += 4) {
                float4 t = *(const float4*)&Bs[k][tcol * TN + j];
                rb[j] = t.x; rb[j + 1] = t.y; rb[j + 2] = t.z; rb[j + 3] = t.w;
            }
            #pragma unroll
            for (int i = 0; i < TM; i++)
                #pragma unroll
                for (int j = 0; j < TN; j++)
                    acc[i][j] = fmaf(ra[i], rb[j], acc[i][j]);
        }
        __syncthreads();
    }

    #pragma unroll
    for (int i = 0; i < TM; i++) {
        int gr = brow + trow * TM + i;
        if (gr >= M) continue;
        #pragma unroll
        for (int j = 0; j < TN; j += 4) {
            int gc = bcol + tcol * TN + j;
            float4 v;
            v.x = acc[i][j]; v.y = acc[i][j + 1]; v.z = acc[i][j + 2]; v.w = acc[i][j + 3];
            if (BIAS) { v.x += bias[gc]; v.y += bias[gc + 1]; v.z += bias[gc + 2]; v.w += bias[gc + 3]; }
            if (RELU) {
                v.x = fmaxf(v.x, 0.f); v.y = fmaxf(v.y, 0.f);
                v.z = fmaxf(v.z, 0.f); v.w = fmaxf(v.w, 0.f);
            }
            *(float4*)(C + (size_t)gr * Ncols + gc) = v;
        }
    }
}

// ---------------- attention score projections (s_src, s_dst) -----------------
template <int HC, int H>
__global__ void k_scores(const float* __restrict__ h, const float* __restrict__ asrc,
                         const float* __restrict__ adst, float* __restrict__ ssrc,
                         float* __restrict__ sdst, int n) {
    constexpr int C = HC / H;
    const int warp = (blockIdx.x * blockDim.x + threadIdx.x) >> 5;
    const int lane = threadIdx.x & 31;
    if (warp >= n) return;
    const float* hp = h + (size_t)warp * HC;
    #pragma unroll
    for (int hh = 0; hh < H; hh++) {
        float ps = 0.f, pd = 0.f;
        #pragma unroll
        for (int c0 = 0; c0 < C; c0 += 32) {
            int c = hh * C + c0 + lane;
            float hv = hp[c];
            ps = fmaf(hv, __ldg(asrc + c), ps);
            pd = fmaf(hv, __ldg(adst + c), pd);
        }
        #pragma unroll
        for (int o = 16; o; o >>= 1) {
            ps += __shfl_down_sync(~0u, ps, o);
            pd += __shfl_down_sync(~0u, pd, o);
        }
        if (lane == 0) { ssrc[warp * H + hh] = ps; sdst[warp * H + hh] = pd; }
    }
}

// ---------------- warp-per-dst GAT softmax + aggregate -----------------------
__device__ __forceinline__ float lrelu(float x) { return x > 0.f ? x : 0.2f * x; }

template <int HC, int H, bool RELU>
__global__ void k_agg(const float* __restrict__ h, const float* __restrict__ ssrc,
                      const float* __restrict__ sdst, const int* __restrict__ off,
                      const int* __restrict__ csr, const float* __restrict__ bias,
                      float* __restrict__ out, int n) {
    constexpr int C = HC / H;
    constexpr int J = HC / 32;
    const int d = (blockIdx.x * blockDim.x + threadIdx.x) >> 5;
    const int lane = threadIdx.x & 31;
    if (d >= n) return;

    float sd[H], es[H], m[H];
    #pragma unroll
    for (int hh = 0; hh < H; hh++) {
        sd[hh] = sdst[d * H + hh];
        es[hh] = lrelu(ssrc[d * H + hh] + sd[hh]);   // self-loop score
        m[hh]  = es[hh];
    }
    const int o0 = off[d], o1 = off[d + 1];

    // pass 1: per-head max
    for (int i = o0 + lane; i < o1; i += 32) {
        int s = csr[i];
        #pragma unroll
        for (int hh = 0; hh < H; hh++)
            m[hh] = fmaxf(m[hh], lrelu(ssrc[s * H + hh] + sd[hh]));
    }
    #pragma unroll
    for (int hh = 0; hh < H; hh++)
        #pragma unroll
        for (int o = 16; o; o >>= 1)
            m[hh] = fmaxf(m[hh], __shfl_xor_sync(~0u, m[hh], o));

    // pass 2: denominator
    float den[H];
    #pragma unroll
    for (int hh = 0; hh < H; hh++) den[hh] = 0.f;
    for (int i = o0 + lane; i < o1; i += 32) {
        int s = csr[i];
        #pragma unroll
        for (int hh = 0; hh < H; hh++)
            den[hh] += __expf(lrelu(ssrc[s * H + hh] + sd[hh]) - m[hh]);
    }
    #pragma unroll
    for (int hh = 0; hh < H; hh++)
        #pragma unroll
        for (int o = 16; o; o >>= 1)
            den[hh] += __shfl_xor_sync(~0u, den[hh], o);

    float invden[H], aself[H];
    #pragma unroll
    for (int hh = 0; hh < H; hh++) {
        float wself = __expf(es[hh] - m[hh]);
        invden[hh] = 1.f / (den[hh] + wself + 1e-16f);
        aself[hh]  = wself * invden[hh];
    }

    // pass 3: weighted aggregate (self loop + edges)
    float acc[J];
    const float* hd = h + (size_t)d * HC;
    #pragma unroll
    for (int j = 0; j < J; j++) {
        int c = j * 32 + lane;
        acc[j] = aself[(j * 32) / C] * hd[c];
    }
    for (int i = o0; i < o1; i++) {
        int s = csr[i];                       // broadcast load
        float al[H];
        #pragma unroll
        for (int hh = 0; hh < H; hh++)
            al[hh] = __expf(lrelu(ssrc[s * H + hh] + sd[hh]) - m[hh]) * invden[hh];
        const float* hs = h + (size_t)s * HC;
        #pragma unroll
        for (int j = 0; j < J; j++) {
            int c = j * 32 + lane;
            acc[j] = fmaf(al[(j * 32) / C], hs[c], acc[j]);
        }
    }
    #pragma unroll
    for (int j = 0; j < J; j++) {
        int c = j * 32 + lane;
        float v = acc[j] + bias[c];
        if (RELU) v = fmaxf(v, 0.f);
        out[(size_t)d * HC + c] = v;
    }
}

// ---------------- reparameterize + split mu / logvar / z ---------------------
__global__ void k_mulvz(const float* __restrict__ aggm, const float* __restrict__ eps,
                        float* __restrict__ o_mu, float* __restrict__ o_lv,
                        float* __restrict__ o_z, int n) {
    int i = blockIdx.x * blockDim.x + threadIdx.x;
    if (i >= n * LATC) return;
    int node = i >> 5, c = i & 31;
    float mu = aggm[node * 64 + c];
    float lv = aggm[node * 64 + 32 + c];
    float z  = mu + eps[i] * expf(0.5f * lv);
    o_mu[i] = mu; o_lv[i] = lv; o_z[i] = z;
}

// ---------------- edge scores -------------------------------------------------
__global__ void k_edge(const float* __restrict__ zd, const int* __restrict__ src,
                       const int* __restrict__ dst, const float* __restrict__ We,
                       const float* __restrict__ be, float* __restrict__ out, int e) {
    const int w = (blockIdx.x * blockDim.x + threadIdx.x) >> 5;
    const int lane = threadIdx.x & 31;
    if (w >= e) return;
    int s = __ldg(&src[w]), d = __ldg(&dst[w]);
    const float* zs = zd + (size_t)s * HIDC;
    const float* zdd = zd + (size_t)d * HIDC;
    float p = zs[lane] * zdd[lane] * __ldg(We + lane)
            + zs[lane + 32] * zdd[lane + 32] * __ldg(We + lane + 32);
    #pragma unroll
    for (int o = 16; o; o >>= 1) p += __shfl_down_sync(~0u, p, o);
    if (lane == 0) out[w] = p + __ldg(be);
}

// ---------------- host driver -------------------------------------------------
extern "C" void kernel_launch(void* const* d_in, const int* in_sizes, int n_in,
                              void* d_out, int out_size) {
    const float* x       = (const float*)d_in[0];
    const int*   ei      = (const int*)d_in[1];   // [2,E]: src row then dst row
    const float* eps     = (const float*)d_in[3];
    const float* W1      = (const float*)d_in[4];
    const float* a_src1  = (const float*)d_in[5];
    const float* a_dst1  = (const float*)d_in[6];
    const float* b1      = (const float*)d_in[7];
    const float* W2      = (const float*)d_in[8];
    const float* a_src2  = (const float*)d_in[9];
    const float* a_dst2  = (const float*)d_in[10];
    const float* b2      = (const float*)d_in[11];
    const float* Wmu     = (const float*)d_in[12];
    const float* a_srcm  = (const float*)d_in[13];
    const float* a_dstm  = (const float*)d_in[14];
    const float* b_mu    = (const float*)d_in[15];
    const float* Wlv     = (const float*)d_in[16];
    const float* a_srcl  = (const float*)d_in[17];
    const float* a_dstl  = (const float*)d_in[18];
    const float* b_lv    = (const float*)d_in[19];
    const float* W_fc    = (const float*)d_in[20];
    const float* b_fc    = (const float*)d_in[21];
    const float* W_node  = (const float*)d_in[22];
    const float* b_node  = (const float*)d_in[23];
    const float* W_edge  = (const float*)d_in[24];
    const float* b_edge  = (const float*)d_in[25];

    const int* e_src = ei;
    const int* e_dst = ei + EE;

    float* out    = (float*)d_out;
    float* o_mu   = out;
    float* o_lv   = out + (size_t)NN * LATC;
    float* o_z    = out + (size_t)2 * NN * LATC;
    float* o_node = out + (size_t)3 * NN * LATC;
    float* o_es   = out + (size_t)3 * NN * LATC + (size_t)NN * INC;

    void *p_hA, *p_hB, *p_hC, *p_aggm, *p_zd, *p_ss, *p_sd;
    void *p_cnt, *p_off, *p_cur, *p_csr, *p_Wml, *p_ams, *p_amd, *p_bml;
    cudaGetSymbolAddress(&p_hA, g_hA);     cudaGetSymbolAddress(&p_hB, g_hB);
    cudaGetSymbolAddress(&p_hC, g_hC);     cudaGetSymbolAddress(&p_aggm, g_aggm);
    cudaGetSymbolAddress(&p_zd, g_zd);     cudaGetSymbolAddress(&p_ss, g_ss);
    cudaGetSymbolAddress(&p_sd, g_sd);     cudaGetSymbolAddress(&p_cnt, g_cnt);
    cudaGetSymbolAddress(&p_off, g_off);   cudaGetSymbolAddress(&p_cur, g_cur);
    cudaGetSymbolAddress(&p_csr, g_csr);   cudaGetSymbolAddress(&p_Wml, g_Wml);
    cudaGetSymbolAddress(&p_ams, g_ams);   cudaGetSymbolAddress(&p_amd, g_amd);
    cudaGetSymbolAddress(&p_bml, g_bml);

    float* hA = (float*)p_hA;  float* hB = (float*)p_hB;  float* hC = (float*)p_hC;
    float* aggm = (float*)p_aggm; float* zd = (float*)p_zd;
    float* ss = (float*)p_ss;  float* sdv = (float*)p_sd;
    int* cnt = (int*)p_cnt; int* off = (int*)p_off; int* cur = (int*)p_cur; int* csr = (int*)p_csr;
    float* Wml = (float*)p_Wml; float* ams = (float*)p_ams; float* amd = (float*)p_amd; float* bml = (float*)p_bml;

    const int TPB = 256;
    const int warpsGrid = (NN + 7) / 8;          // 8 warps per 256-thread block
    const int edgeWarpsGrid = (EE + 7) / 8;

    // ---- CSR build (real edges only; self-loops handled analytically) ----
    k_zero<<<(NN + TPB - 1) / TPB, TPB>>>(cnt, NN);
    k_deg<<<(EE + TPB - 1) / TPB, TPB>>>(e_dst, cnt, EE);
    k_scan<<<1, 1024>>>(cnt, off, cur, NN);
    k_scatter<<<(EE + TPB - 1) / TPB, TPB>>>(e_src, e_dst, cur, csr, EE);

    dim3 gridWide((NN + 127) / 128, 2);  // N=256 GEMMs
    dim3 gridN64((NN + 127) / 128, 1);   // N=64 GEMMs

    // ---- conv1 ----
    k_gemm<128, 128, 32, 8, 8, false, false><<<gridWide, 256>>>(x, W1, nullptr, hA, NN, 256, 64);
    k_scores<HC1, NH><<<warpsGrid, TPB>>>(hA, a_src1, a_dst1, ss, sdv, NN);
    k_agg<HC1, NH, true><<<warpsGrid, TPB>>>(hA, ss, sdv, off, csr, b1, hB, NN);

    // ---- conv2 ----
    k_gemm<128, 128, 32, 8, 8, false, false><<<gridWide, 256>>>(hB, W2, nullptr, hA, NN, 256, 256);
    k_scores<HC1, NH><<<warpsGrid, TPB>>>(hA, a_src2, a_dst2, ss, sdv, NN);
    k_agg<HC1, NH, true><<<warpsGrid, TPB>>>(hA, ss, sdv, off, csr, b2, hB, NN);

    // ---- fused mu|lv layer (2 independent heads of width 32) ----
    k_pack<<<(HC1 * HCM + TPB - 1) / TPB, TPB>>>(Wmu, Wlv, a_srcm, a_srcl, a_dstm, a_dstl, b_mu, b_lv);
    k_gemm<128, 64, 32, 8, 4, false, false><<<gridN64, 256>>>(hB, Wml, nullptr, hC, NN, 64, 256);
    k_scores<HCM, 2><<<warpsGrid, TPB>>>(hC, ams, amd, ss, sdv, NN);
    k_agg<HCM, 2, false><<<warpsGrid, TPB>>>(hC, ss, sdv, off, csr, bml, aggm, NN);

    // ---- reparameterize ----
    k_mulvz<<<(NN * LATC + TPB - 1) / TPB, TPB>>>(aggm, eps, o_mu, o_lv, o_z, NN);

    // ---- decoder ----
    k_gemm<128, 64, 32, 8, 4, true, true><<<gridN64, 256>>>(o_z, W_fc, b_fc, zd, NN, 64, 32);
    k_gemm<128, 64, 32, 8, 4, true, false><<<gridN64, 256>>>(zd, W_node, b_node, o_node, NN, 64, 64);
    k_edge<<<edgeWarpsGrid, TPB>>>(zd, e_src, e_dst, W_edge, b_edge, o_es, EE);
}

// round 3
// speedup vs baseline: 1.2479x; 1.2479x over previous
#include <cuda_runtime.h>
#include <cuda_bf16.h>
#include <cstdint>
#include <cstdio>

// Problem constants
#define NN   50000
#define EE   400000
#define INC  64
#define HIDC 64
#define NH   4
#define LATC 32
#define HC1  256   // H*HID for conv1/conv2 outputs
#define HCM  64    // combined mu|lv width (2 heads x 32)

// ---------------- scratch (static device globals; no allocation) ------------
__device__ float g_hA[(size_t)NN * HC1];   // GEMM output (pre-attention h)
__device__ float g_hB[(size_t)NN * HC1];   // aggregated layer output
__device__ float g_hC[(size_t)NN * HCM];   // mu|lv GEMM output
__device__ float g_aggm[(size_t)NN * HCM]; // mu|lv aggregated (+bias)
__device__ float g_zd[(size_t)NN * HIDC];  // decoder hidden
__device__ float g_ss[NN * NH];            // s_src
__device__ float g_sd[NN * NH];            // s_dst
__device__ int   g_cnt[NN];
__device__ int   g_off[NN + 1];
__device__ int   g_cur[NN];
__device__ int   g_csr[EE];
__device__ float g_Wml[HCM * HC1];         // fused [Wmu|Wlv] TRANSPOSED: [64 rows, 256]
__device__ float g_ams[HCM];
__device__ float g_amd[HCM];
__device__ float g_bml[HCM];
__device__ float g_Wt1[HC1 * INC];         // W1^T  [256,64]
__device__ float g_Wt2[HC1 * HC1];         // W2^T  [256,256]
__device__ float g_Wfct[HIDC * LATC];      // W_fc^T [64,32]
__device__ float g_Wnt[INC * HIDC];        // W_node^T [64,64]

// ---------------- bf16 split helpers ----------------------------------------
__device__ __forceinline__ void bf16_split(float x, uint16_t& hi, uint16_t& lo) {
    __nv_bfloat16 h = __float2bfloat16_rn(x);
    float r = x - __bfloat162float(h);
    __nv_bfloat16 l = __float2bfloat16_rn(r);
    hi = *(uint16_t*)&h;
    lo = *(uint16_t*)&l;
}

__device__ __forceinline__ void mma_bf16(float* c, const uint32_t* a, const uint32_t* b) {
    asm volatile(
        "mma.sync.aligned.m16n8k16.row.col.f32.bf16.bf16.f32 "
        "{%0,%1,%2,%3}, {%4,%5,%6,%7}, {%8,%9}, {%0,%1,%2,%3};"
        : "+f"(c[0]), "+f"(c[1]), "+f"(c[2]), "+f"(c[3])
        : "r"(a[0]), "r"(a[1]), "r"(a[2]), "r"(a[3]), "r"(b[0]), "r"(b[1]));
}

// ---------------- tensor-core split-bf16 GEMM: C[M,N] = A[M,K] @ Bt[N,K]^T ---
// 3-term: D = Ah*Bh + Ah*Bl + Al*Bh  (~1e-5 relative accuracy).
// CTA: 256 thr = 8 warps (4m x 2n), tile BM=128 x BN=64, BK=32 chunks.
template <int N, int K, bool BIAS, bool RELU>
__global__ void __launch_bounds__(256)
k_mma_gemm(const float* __restrict__ A, const float* __restrict__ Bt,
           const float* __restrict__ bias, float* __restrict__ C, int M) {
    constexpr int BM = 128, BN = 64, BK = 32;
    constexpr int NCH = K / BK;
    constexpr int AST = BK + 8;     // 40-half stride (bank stagger)

    __shared__ uint16_t sAh[BM][AST], sAl[BM][AST];
    __shared__ uint16_t sBh[BN][AST], sBl[BN][AST];

    const int tid = threadIdx.x;
    const int tile_m = blockIdx.x * BM;
    const int tile_n = blockIdx.y * BN;
    const int wid = tid >> 5, lane = tid & 31;
    const int wm = wid >> 1, wn = wid & 1;    // warp tile 32(m) x 32(n)
    const int g = lane >> 2, tg = lane & 3;

    float acc[2][4][4];
    #pragma unroll
    for (int mt = 0; mt < 2; mt++)
        #pragma unroll
        for (int nt = 0; nt < 4; nt++)
            #pragma unroll
            for (int j = 0; j < 4; j++) acc[mt][nt][j] = 0.f;

    for (int kt = 0; kt < K; kt += BK) {
        // ---- load + split A tile (128x32 f32 -> hi/lo bf16) ----
        #pragma unroll
        for (int l = 0; l < 4; l++) {
            int v = tid + l * 256;            // 1024 float4 total
            int row = v >> 3, c4 = (v & 7) * 4;
            int gr = tile_m + row;
            float4 a = (gr < M) ? *(const float4*)(A + (size_t)gr * K + kt + c4)
                                : make_float4(0.f, 0.f, 0.f, 0.f);
            uint16_t h0, h1, h2, h3, l0, l1, l2, l3;
            bf16_split(a.x, h0, l0); bf16_split(a.y, h1, l1);
            bf16_split(a.z, h2, l2); bf16_split(a.w, h3, l3);
            *(uint32_t*)&sAh[row][c4]     = (uint32_t)h0 | ((uint32_t)h1 << 16);
            *(uint32_t*)&sAh[row][c4 + 2] = (uint32_t)h2 | ((uint32_t)h3 << 16);
            *(uint32_t*)&sAl[row][c4]     = (uint32_t)l0 | ((uint32_t)l1 << 16);
            *(uint32_t*)&sAl[row][c4 + 2] = (uint32_t)l2 | ((uint32_t)l3 << 16);
        }
        // ---- load + split B tile (64x32 f32 from Bt[N,K]) ----
        #pragma unroll
        for (int l = 0; l < 2; l++) {
            int v = tid + l * 256;            // 512 float4 total
            int row = v >> 3, c4 = (v & 7) * 4;
            float4 a = *(const float4*)(Bt + (size_t)(tile_n + row) * K + kt + c4);
            uint16_t h0, h1, h2, h3, l0, l1, l2, l3;
            bf16_split(a.x, h0, l0); bf16_split(a.y, h1, l1);
            bf16_split(a.z, h2, l2); bf16_split(a.w, h3, l3);
            *(uint32_t*)&sBh[row][c4]     = (uint32_t)h0 | ((uint32_t)h1 << 16);
            *(uint32_t*)&sBh[row][c4 + 2] = (uint32_t)h2 | ((uint32_t)h3 << 16);
            *(uint32_t*)&sBl[row][c4]     = (uint32_t)l0 | ((uint32_t)l1 << 16);
            *(uint32_t*)&sBl[row][c4 + 2] = (uint32_t)l2 | ((uint32_t)l3 << 16);
        }
        __syncthreads();

        // ---- compute: 2 k16 steps per chunk ----
        #pragma unroll
        for (int ks = 0; ks < 2; ks++) {
            const int k0 = ks * 16;
            uint32_t ah[2][4], al[2][4], bh[4][2], bl[4][2];
            #pragma unroll
            for (int mt = 0; mt < 2; mt++) {
                int r0 = wm * 32 + mt * 16 + g;
                ah[mt][0] = *(const uint32_t*)&sAh[r0][k0 + 2 * tg];
                ah[mt][1] = *(const uint32_t*)&sAh[r0 + 8][k0 + 2 * tg];
                ah[mt][2] = *(const uint32_t*)&sAh[r0][k0 + 2 * tg + 8];
                ah[mt][3] = *(const uint32_t*)&sAh[r0 + 8][k0 + 2 * tg + 8];
                al[mt][0] = *(const uint32_t*)&sAl[r0][k0 + 2 * tg];
                al[mt][1] = *(const uint32_t*)&sAl[r0 + 8][k0 + 2 * tg];
                al[mt][2] = *(const uint32_t*)&sAl[r0][k0 + 2 * tg + 8];
                al[mt][3] = *(const uint32_t*)&sAl[r0 + 8][k0 + 2 * tg + 8];
            }
            #pragma unroll
            for (int nt = 0; nt < 4; nt++) {
                int n0 = wn * 32 + nt * 8 + g;
                bh[nt][0] = *(const uint32_t*)&sBh[n0][k0 + 2 * tg];
                bh[nt][1] = *(const uint32_t*)&sBh[n0][k0 + 2 * tg + 8];
                bl[nt][0] = *(const uint32_t*)&sBl[n0][k0 + 2 * tg];
                bl[nt][1] = *(const uint32_t*)&sBl[n0][k0 + 2 * tg + 8];
            }
            #pragma unroll
            for (int mt = 0; mt < 2; mt++)
                #pragma unroll
                for (int nt = 0; nt < 4; nt++) {
                    mma_bf16(acc[mt][nt], ah[mt], bh[nt]);
                    mma_bf16(acc[mt][nt], ah[mt], bl[nt]);
                    mma_bf16(acc[mt][nt], al[mt], bh[nt]);
                }
        }
        __syncthreads();
    }

    // ---- epilogue ----
    #pragma unroll
    for (int mt = 0; mt < 2; mt++) {
        #pragma unroll
        for (int nt = 0; nt < 4; nt++) {
            int col = tile_n + wn * 32 + nt * 8 + 2 * tg;
            float b0 = 0.f, b1 = 0.f;
            if (BIAS) { b0 = __ldg(bias + col); b1 = __ldg(bias + col + 1); }
            int r0 = tile_m + wm * 32 + mt * 16 + g;
            #pragma unroll
            for (int half = 0; half < 2; half++) {
                int row = r0 + half * 8;
                if (row < M) {
                    float v0 = acc[mt][nt][half * 2 + 0] + b0;
                    float v1 = acc[mt][nt][half * 2 + 1] + b1;
                    if (RELU) { v0 = fmaxf(v0, 0.f); v1 = fmaxf(v1, 0.f); }
                    float2 v = make_float2(v0, v1);
                    *(float2*)(C + (size_t)row * N + col) = v;
                }
            }
        }
    }
}

// ---------------- small utility kernels -------------------------------------
__global__ void k_zero(int* c, int n) {
    int i = blockIdx.x * blockDim.x + threadIdx.x;
    if (i < n) c[i] = 0;
}

__global__ void k_deg(const int* __restrict__ dst, int* __restrict__ cnt, int e) {
    int i = blockIdx.x * blockDim.x + threadIdx.x;
    if (i < e) atomicAdd(&cnt[dst[i]], 1);
}

__global__ void k_scan(const int* __restrict__ cnt, int* __restrict__ off,
                       int* __restrict__ cur, int n) {
    __shared__ int warpsums[32];
    __shared__ int s_carry;
    const int tid = threadIdx.x, lane = tid & 31, wid = tid >> 5;
    if (tid == 0) s_carry = 0;
    __syncthreads();
    for (int base = 0; base < n; base += blockDim.x) {
        int i = base + tid;
        int v = (i < n) ? cnt[i] : 0;
        int x = v;
        #pragma unroll
        for (int o = 1; o < 32; o <<= 1) {
            int t = __shfl_up_sync(~0u, x, o);
            if (lane >= o) x += t;
        }
        if (lane == 31) warpsums[wid] = x;
        __syncthreads();
        if (wid == 0) {
            int w = warpsums[lane];
            #pragma unroll
            for (int o = 1; o < 32; o <<= 1) {
                int t = __shfl_up_sync(~0u, w, o);
                if (lane >= o) w += t;
            }
            warpsums[lane] = w;
        }
        __syncthreads();
        int warpoff = (wid == 0) ? 0 : warpsums[wid - 1];
        int carry = s_carry;
        int excl = carry + warpoff + x - v;
        if (i < n) { off[i] = excl; cur[i] = excl; }
        __syncthreads();
        if (tid == blockDim.x - 1) s_carry = carry + warpsums[31];
        __syncthreads();
    }
    if (tid == 0) off[n] = s_carry;
}

__global__ void k_scatter(const int* __restrict__ src, const int* __restrict__ dst,
                          int* __restrict__ cur, int* __restrict__ csr, int e) {
    int i = blockIdx.x * blockDim.x + threadIdx.x;
    if (i < e) {
        int d = dst[i];
        int p = atomicAdd(&cur[d], 1);
        csr[p] = src[i];
    }
}

// transpose B[K,N] -> Bt[N,K]
__global__ void k_transpose(const float* __restrict__ B, float* __restrict__ Bt,
                            int K, int Ncols) {
    int i = blockIdx.x * blockDim.x + threadIdx.x;
    if (i < K * Ncols) {
        int k = i / Ncols, nn = i % Ncols;
        Bt[nn * K + k] = B[i];
    }
}

// pack fused mu|lv weights TRANSPOSED [64, 256] + concat a / bias vectors
__global__ void k_pack(const float* __restrict__ Wmu, const float* __restrict__ Wlv,
                       const float* __restrict__ asmu, const float* __restrict__ aslv,
                       const float* __restrict__ admu, const float* __restrict__ adlv,
                       const float* __restrict__ bmu, const float* __restrict__ blv) {
    int i = blockIdx.x * blockDim.x + threadIdx.x;
    if (i < HC1 * HCM) {
        int k = i >> 6, c = i & 63;
        g_Wml[c * HC1 + k] = (c < 32) ? Wmu[k * 32 + c] : Wlv[k * 32 + (c - 32)];
    }
    if (i < HCM) {
        g_ams[i] = (i < 32) ? asmu[i] : aslv[i - 32];
        g_amd[i] = (i < 32) ? admu[i] : adlv[i - 32];
        g_bml[i] = (i < 32) ? bmu[i]  : blv[i - 32];
    }
}

// ---------------- attention score projections (s_src, s_dst) -----------------
template <int HC, int H>
__global__ void k_scores(const float* __restrict__ h, const float* __restrict__ asrc,
                         const float* __restrict__ adst, float* __restrict__ ssrc,
                         float* __restrict__ sdst, int n) {
    constexpr int C = HC / H;
    const int warp = (blockIdx.x * blockDim.x + threadIdx.x) >> 5;
    const int lane = threadIdx.x & 31;
    if (warp >= n) return;
    const float* hp = h + (size_t)warp * HC;
    #pragma unroll
    for (int hh = 0; hh < H; hh++) {
        float ps = 0.f, pd = 0.f;
        #pragma unroll
        for (int c0 = 0; c0 < C; c0 += 32) {
            int c = hh * C + c0 + lane;
            float hv = hp[c];
            ps = fmaf(hv, __ldg(asrc + c), ps);
            pd = fmaf(hv, __ldg(adst + c), pd);
        }
        #pragma unroll
        for (int o = 16; o; o >>= 1) {
            ps += __shfl_down_sync(~0u, ps, o);
            pd += __shfl_down_sync(~0u, pd, o);
        }
        if (lane == 0) { ssrc[warp * H + hh] = ps; sdst[warp * H + hh] = pd; }
    }
}

// ---------------- warp-per-dst GAT softmax + aggregate -----------------------
__device__ __forceinline__ float lrelu(float x) { return x > 0.f ? x : 0.2f * x; }

template <int HC, int H, bool RELU>
__global__ void k_agg(const float* __restrict__ h, const float* __restrict__ ssrc,
                      const float* __restrict__ sdst, const int* __restrict__ off,
                      const int* __restrict__ csr, const float* __restrict__ bias,
                      float* __restrict__ out, int n) {
    constexpr int C = HC / H;
    constexpr int J = HC / 32;
    const int d = (blockIdx.x * blockDim.x + threadIdx.x) >> 5;
    const int lane = threadIdx.x & 31;
    if (d >= n) return;

    float sd[H], es[H], m[H];
    #pragma unroll
    for (int hh = 0; hh < H; hh++) {
        sd[hh] = sdst[d * H + hh];
        es[hh] = lrelu(ssrc[d * H + hh] + sd[hh]);
        m[hh]  = es[hh];
    }
    const int o0 = off[d], o1 = off[d + 1];

    for (int i = o0 + lane; i < o1; i += 32) {
        int s = csr[i];
        #pragma unroll
        for (int hh = 0; hh < H; hh++)
            m[hh] = fmaxf(m[hh], lrelu(ssrc[s * H + hh] + sd[hh]));
    }
    #pragma unroll
    for (int hh = 0; hh < H; hh++)
        #pragma unroll
        for (int o = 16; o; o >>= 1)
            m[hh] = fmaxf(m[hh], __shfl_xor_sync(~0u, m[hh], o));

    float den[H];
    #pragma unroll
    for (int hh = 0; hh < H; hh++) den[hh] = 0.f;
    for (int i = o0 + lane; i < o1; i += 32) {
        int s = csr[i];
        #pragma unroll
        for (int hh = 0; hh < H; hh++)
            den[hh] += __expf(lrelu(ssrc[s * H + hh] + sd[hh]) - m[hh]);
    }
    #pragma unroll
    for (int hh = 0; hh < H; hh++)
        #pragma unroll
        for (int o = 16; o; o >>= 1)
            den[hh] += __shfl_xor_sync(~0u, den[hh], o);

    float invden[H], aself[H];
    #pragma unroll
    for (int hh = 0; hh < H; hh++) {
        float wself = __expf(es[hh] - m[hh]);
        invden[hh] = 1.f / (den[hh] + wself + 1e-16f);
        aself[hh]  = wself * invden[hh];
    }

    float acc[J];
    const float* hd = h + (size_t)d * HC;
    #pragma unroll
    for (int j = 0; j < J; j++) {
        int c = j * 32 + lane;
        acc[j] = aself[(j * 32) / C] * hd[c];
    }
    for (int i = o0; i < o1; i++) {
        int s = csr[i];
        float al[H];
        #pragma unroll
        for (int hh = 0; hh < H; hh++)
            al[hh] = __expf(lrelu(ssrc[s * H + hh] + sd[hh]) - m[hh]) * invden[hh];
        const float* hs = h + (size_t)s * HC;
        #pragma unroll
        for (int j = 0; j < J; j++) {
            int c = j * 32 + lane;
            acc[j] = fmaf(al[(j * 32) / C], hs[c], acc[j]);
        }
    }
    #pragma unroll
    for (int j = 0; j < J; j++) {
        int c = j * 32 + lane;
        float v = acc[j] + bias[c];
        if (RELU) v = fmaxf(v, 0.f);
        out[(size_t)d * HC + c] = v;
    }
}

// ---------------- reparameterize + split mu / logvar / z ---------------------
__global__ void k_mulvz(const float* __restrict__ aggm, const float* __restrict__ eps,
                        float* __restrict__ o_mu, float* __restrict__ o_lv,
                        float* __restrict__ o_z, int n) {
    int i = blockIdx.x * blockDim.x + threadIdx.x;
    if (i >= n * LATC) return;
    int node = i >> 5, c = i & 31;
    float mu = aggm[node * 64 + c];
    float lv = aggm[node * 64 + 32 + c];
    float z  = mu + eps[i] * expf(0.5f * lv);
    o_mu[i] = mu; o_lv[i] = lv; o_z[i] = z;
}

// ---------------- edge scores -------------------------------------------------
__global__ void k_edge(const float* __restrict__ zd, const int* __restrict__ src,
                       const int* __restrict__ dst, const float* __restrict__ We,
                       const float* __restrict__ be, float* __restrict__ out, int e) {
    const int w = (blockIdx.x * blockDim.x + threadIdx.x) >> 5;
    const int lane = threadIdx.x & 31;
    if (w >= e) return;
    int s = __ldg(&src[w]), d = __ldg(&dst[w]);
    const float* zs = zd + (size_t)s * HIDC;
    const float* zdd = zd + (size_t)d * HIDC;
    float p = zs[lane] * zdd[lane] * __ldg(We + lane)
            + zs[lane + 32] * zdd[lane + 32] * __ldg(We + lane + 32);
    #pragma unroll
    for (int o = 16; o; o >>= 1) p += __shfl_down_sync(~0u, p, o);
    if (lane == 0) out[w] = p + __ldg(be);
}

// ---------------- host driver -------------------------------------------------
extern "C" void kernel_launch(void* const* d_in, const int* in_sizes, int n_in,
                              void* d_out, int out_size) {
    const float* x       = (const float*)d_in[0];
    const int*   ei      = (const int*)d_in[1];
    const float* eps     = (const float*)d_in[3];
    const float* W1      = (const float*)d_in[4];
    const float* a_src1  = (const float*)d_in[5];
    const float* a_dst1  = (const float*)d_in[6];
    const float* b1      = (const float*)d_in[7];
    const float* W2      = (const float*)d_in[8];
    const float* a_src2  = (const float*)d_in[9];
    const float* a_dst2  = (const float*)d_in[10];
    const float* b2      = (const float*)d_in[11];
    const float* Wmu     = (const float*)d_in[12];
    const float* a_srcm  = (const float*)d_in[13];
    const float* a_dstm  = (const float*)d_in[14];
    const float* b_mu    = (const float*)d_in[15];
    const float* Wlv     = (const float*)d_in[16];
    const float* a_srcl  = (const float*)d_in[17];
    const float* a_dstl  = (const float*)d_in[18];
    const float* b_lv    = (const float*)d_in[19];
    const float* W_fc    = (const float*)d_in[20];
    const float* b_fc    = (const float*)d_in[21];
    const float* W_node  = (const float*)d_in[22];
    const float* b_node  = (const float*)d_in[23];
    const float* W_edge  = (const float*)d_in[24];
    const float* b_edge  = (const float*)d_in[25];

    const int* e_src = ei;
    const int* e_dst = ei + EE;

    float* out    = (float*)d_out;
    float* o_mu   = out;
    float* o_lv   = out + (size_t)NN * LATC;
    float* o_z    = out + (size_t)2 * NN * LATC;
    float* o_node = out + (size_t)3 * NN * LATC;
    float* o_es   = out + (size_t)3 * NN * LATC + (size_t)NN * INC;

    void *p_hA, *p_hB, *p_hC, *p_aggm, *p_zd, *p_ss, *p_sd;
    void *p_cnt, *p_off, *p_cur, *p_csr, *p_Wml, *p_ams, *p_amd, *p_bml;
    void *p_Wt1, *p_Wt2, *p_Wfct, *p_Wnt;
    cudaGetSymbolAddress(&p_hA, g_hA);     cudaGetSymbolAddress(&p_hB, g_hB);
    cudaGetSymbolAddress(&p_hC, g_hC);     cudaGetSymbolAddress(&p_aggm, g_aggm);
    cudaGetSymbolAddress(&p_zd, g_zd);     cudaGetSymbolAddress(&p_ss, g_ss);
    cudaGetSymbolAddress(&p_sd, g_sd);     cudaGetSymbolAddress(&p_cnt, g_cnt);
    cudaGetSymbolAddress(&p_off, g_off);   cudaGetSymbolAddress(&p_cur, g_cur);
    cudaGetSymbolAddress(&p_csr, g_csr);   cudaGetSymbolAddress(&p_Wml, g_Wml);
    cudaGetSymbolAddress(&p_ams, g_ams);   cudaGetSymbolAddress(&p_amd, g_amd);
    cudaGetSymbolAddress(&p_bml, g_bml);
    cudaGetSymbolAddress(&p_Wt1, g_Wt1);   cudaGetSymbolAddress(&p_Wt2, g_Wt2);
    cudaGetSymbolAddress(&p_Wfct, g_Wfct); cudaGetSymbolAddress(&p_Wnt, g_Wnt);

    float* hA = (float*)p_hA;  float* hB = (float*)p_hB;  float* hC = (float*)p_hC;
    float* aggm = (float*)p_aggm; float* zd = (float*)p_zd;
    float* ss = (float*)p_ss;  float* sdv = (float*)p_sd;
    int* cnt = (int*)p_cnt; int* off = (int*)p_off; int* cur = (int*)p_cur; int* csr = (int*)p_csr;
    float* Wml = (float*)p_Wml; float* ams = (float*)p_ams; float* amd = (float*)p_amd; float* bml = (float*)p_bml;
    float* Wt1 = (float*)p_Wt1; float* Wt2 = (float*)p_Wt2;
    float* Wfct = (float*)p_Wfct; float* Wnt = (float*)p_Wnt;

    const int TPB = 256;
    const int warpsGrid = (NN + 7) / 8;
    const int edgeWarpsGrid = (EE + 7) / 8;
    const int gm = (NN + 127) / 128;

    // ---- CSR build ----
    k_zero<<<(NN + TPB - 1) / TPB, TPB>>>(cnt, NN);
    k_deg<<<(EE + TPB - 1) / TPB, TPB>>>(e_dst, cnt, EE);
    k_scan<<<1, 1024>>>(cnt, off, cur, NN);
    k_scatter<<<(EE + TPB - 1) / TPB, TPB>>>(e_src, e_dst, cur, csr, EE);

    // ---- weight transposes (tiny) ----
    k_transpose<<<(64 * 256 + TPB - 1) / TPB, TPB>>>(W1, Wt1, 64, 256);
    k_transpose<<<(256 * 256 + TPB - 1) / TPB, TPB>>>(W2, Wt2, 256, 256);
    k_pack<<<(HC1 * HCM + TPB - 1) / TPB, TPB>>>(Wmu, Wlv, a_srcm, a_srcl, a_dstm, a_dstl, b_mu, b_lv);
    k_transpose<<<(32 * 64 + TPB - 1) / TPB, TPB>>>(W_fc, Wfct, 32, 64);
    k_transpose<<<(64 * 64 + TPB - 1) / TPB, TPB>>>(W_node, Wnt, 64, 64);

    // ---- conv1 ----
    k_mma_gemm<256, 64, false, false><<<dim3(gm, 4), 256>>>(x, Wt1, nullptr, hA, NN);
    k_scores<HC1, NH><<<warpsGrid, TPB>>>(hA, a_src1, a_dst1, ss, sdv, NN);
    k_agg<HC1, NH, true><<<warpsGrid, TPB>>>(hA, ss, sdv, off, csr, b1, hB, NN);

    // ---- conv2 ----
    k_mma_gemm<256, 256, false, false><<<dim3(gm, 4), 256>>>(hB, Wt2, nullptr, hA, NN);
    k_scores<HC1, NH><<<warpsGrid, TPB>>>(hA, a_src2, a_dst2, ss, sdv, NN);
    k_agg<HC1, NH, true><<<warpsGrid, TPB>>>(hA, ss, sdv, off, csr, b2, hB, NN);

    // ---- fused mu|lv layer ----
    k_mma_gemm<64, 256, false, false><<<dim3(gm, 1), 256>>>(hB, Wml, nullptr, hC, NN);
    k_scores<HCM, 2><<<warpsGrid, TPB>>>(hC, ams, amd, ss, sdv, NN);
    k_agg<HCM, 2, false><<<warpsGrid, TPB>>>(hC, ss, sdv, off, csr, bml, aggm, NN);

    // ---- reparameterize ----
    k_mulvz<<<(NN * LATC + TPB - 1) / TPB, TPB>>>(aggm, eps, o_mu, o_lv, o_z, NN);

    // ---- decoder ----
    k_mma_gemm<64, 32, true, true><<<dim3(gm, 1), 256>>>(o_z, Wfct, b_fc, zd, NN);
    k_mma_gemm<64, 64, true, false><<<dim3(gm, 1), 256>>>(zd, Wnt, b_node, o_node, NN);
    k_edge<<<edgeWarpsGrid, TPB>>>(zd, e_src, e_dst, W_edge, b_edge, o_es, EE);
}